// round 6
// baseline (speedup 1.0000x reference)
#include <cuda_runtime.h>
#include <cstdint>
#include <cstddef>

constexpr int B=256, T=64, H=512, D=2048, S=32, C=32, A_=32, E=1024, BS=256;
constexpr int X3H=1536, INX=1056, G3=768, NG=6144, DE_IN=3072, SC=1024;
constexpr int NBLK=444, NTH=256;   // 3 blocks/SM x 148 SMs

__device__ __align__(16) float g_deter[B*D];
__device__ __align__(16) float g_xin [B*INX];
__device__ __align__(16) float g_x   [B*X3H];
__device__ __align__(16) float g_h   [B*D];
__device__ __align__(16) float g_gi  [B*NG];
__device__ __align__(16) float g_gh  [B*NG];
__device__ __align__(16) float g_h1c [2*B*H];   // rows 0..255 prior, 256..511 post
__device__ __align__(16) float g_h2c [2*B*H];
__device__ __align__(16) float g_dein[B*DE_IN];
__device__ __align__(16) float g_de  [B*D];
__device__ unsigned g_cnt;
__device__ unsigned g_gen;
__device__ unsigned g_ctr[6*T];   // dynamic tile counters, reset each launch

// ----------------------------- grid barrier --------------------------------
__device__ __forceinline__ void gridbar() {
  __syncthreads();
  if (threadIdx.x == 0) {
    unsigned gen = *(volatile unsigned*)&g_gen;
    __threadfence();
    if (atomicAdd(&g_cnt, 1u) == gridDim.x - 1u) {
      g_cnt = 0u;
      __threadfence();
      atomicExch(&g_gen, gen + 1u);
    } else {
      while (*(volatile unsigned*)&g_gen == gen) {}
    }
    __threadfence();
  }
  __syncthreads();
}

// ------------------------------ threefry2x32 -------------------------------
__device__ __forceinline__ void threefry(uint32_t k0, uint32_t k1, uint32_t x0,
                                         uint32_t x1, uint32_t& o0, uint32_t& o1) {
  uint32_t ks2 = 0x1BD11BDAu ^ k0 ^ k1;
#define TFR(x,r) x = (x<<r)|(x>>(32-r))
#define TF4(a,b,c,d) x0+=x1;TFR(x1,a);x1^=x0; x0+=x1;TFR(x1,b);x1^=x0; x0+=x1;TFR(x1,c);x1^=x0; x0+=x1;TFR(x1,d);x1^=x0;
  x0 += k0; x1 += k1;
  TF4(13,15,26,6);  x0 += k1;  x1 += ks2 + 1u;
  TF4(17,29,16,24); x0 += ks2; x1 += k0 + 2u;
  TF4(13,15,26,6);  x0 += k0;  x1 += k1 + 3u;
  TF4(17,29,16,24); x0 += k1;  x1 += ks2 + 4u;
  TF4(13,15,26,6);  x0 += ks2; x1 += k0 + 5u;
  o0 = x0; o1 = x1;
#undef TF4
#undef TFR
}

// ------------------------------ GEMM tile ----------------------------------
// C[m,n] = sum_k A[m,k]*W[n,k] + bias[n], 64x64 tile, BK=16, 256 threads,
// 4x4 per-thread register tile, global loads register-prefetched.
template <int ACT, int MASKED>
__device__ __forceinline__ void gemm_tile(
    const float* __restrict__ A, int lda, const float* __restrict__ W,
    const float* __restrict__ bias, float* __restrict__ Cb, int ldc,
    int IN, int m0, int n0, int aColBase,
    const int* __restrict__ isf, int t,
    float (*As)[68], float (*Ws)[68], float* mrow) {
  const int tid = threadIdx.x;
  if (MASKED) { if (tid < 64) mrow[tid] = isf[(size_t)(m0+tid)*T + t] ? 0.0f : 1.0f; }
  __syncthreads();
  const float* Ab = A + (size_t)m0*lda + aColBase;
  const float* Wb = W + (size_t)n0*IN;
  const int lr = tid>>2, lq = (tid&3)<<2, ty = tid>>4, tx = tid&15;
  float acc[4][4] = {};
  float4 av = *(const float4*)(Ab + (size_t)lr*lda + lq);
  float4 wv = *(const float4*)(Wb + (size_t)lr*IN + lq);
  for (int k0 = 0; k0 < IN; k0 += 16) {
    float mm = MASKED ? mrow[lr] : 1.0f;
    As[lq+0][lr]=av.x*mm; As[lq+1][lr]=av.y*mm;
    As[lq+2][lr]=av.z*mm; As[lq+3][lr]=av.w*mm;
    Ws[lq+0][lr]=wv.x; Ws[lq+1][lr]=wv.y; Ws[lq+2][lr]=wv.z; Ws[lq+3][lr]=wv.w;
    __syncthreads();
    if (k0 + 16 < IN) {
      av = *(const float4*)(Ab + (size_t)lr*lda + k0 + 16 + lq);
      wv = *(const float4*)(Wb + (size_t)lr*IN + k0 + 16 + lq);
    }
#pragma unroll
    for (int kk = 0; kk < 16; kk++) {
      float4 a = *(const float4*)&As[kk][ty<<2];
      float4 w = *(const float4*)&Ws[kk][tx<<2];
      acc[0][0]+=a.x*w.x; acc[0][1]+=a.x*w.y; acc[0][2]+=a.x*w.z; acc[0][3]+=a.x*w.w;
      acc[1][0]+=a.y*w.x; acc[1][1]+=a.y*w.y; acc[1][2]+=a.y*w.z; acc[1][3]+=a.y*w.w;
      acc[2][0]+=a.z*w.x; acc[2][1]+=a.z*w.y; acc[2][2]+=a.z*w.z; acc[2][3]+=a.z*w.w;
      acc[3][0]+=a.w*w.x; acc[3][1]+=a.w*w.y; acc[3][2]+=a.w*w.z; acc[3][3]+=a.w*w.w;
    }
    __syncthreads();
  }
#pragma unroll
  for (int r = 0; r < 4; r++) {
    int mi = m0 + (ty<<2) + r;
    int nb = n0 + (tx<<2);
    float4 bv = *(const float4*)(bias + nb);
    float4 v;
    v.x = acc[r][0] + bv.x; v.y = acc[r][1] + bv.y;
    v.z = acc[r][2] + bv.z; v.w = acc[r][3] + bv.w;
    if (ACT) {
      v.x = v.x/(1.0f+expf(-v.x)); v.y = v.y/(1.0f+expf(-v.y));
      v.z = v.z/(1.0f+expf(-v.z)); v.w = v.w/(1.0f+expf(-v.w));
    }
    *(float4*)(Cb + (size_t)mi*ldc + nb) = v;
  }
}

// ------------------------------ megakernel ---------------------------------
__global__ void __launch_bounds__(NTH, 3) k_rssm(
    const float* __restrict__ embed, const float* __restrict__ actions,
    const int* __restrict__ isf,
    const float* __restrict__ W_in,  const float* __restrict__ b_in,
    const float* __restrict__ W_blk, const float* __restrict__ b_blk,
    const float* __restrict__ W_ih,  const float* __restrict__ b_ih,
    const float* __restrict__ W_hh,  const float* __restrict__ b_hh,
    const float* __restrict__ W1,    const float* __restrict__ b1,
    const float* __restrict__ W2,    const float* __restrict__ b2,
    const float* __restrict__ W3,    const float* __restrict__ b3,
    const float* __restrict__ W_proj,const float* __restrict__ b_proj,
    float* __restrict__ out_deter, float* __restrict__ out_stoch,
    float* __restrict__ out_prior, float* __restrict__ out_post) {
  __shared__ __align__(16) float As[16][68];
  __shared__ __align__(16) float Ws[16][68];
  __shared__ float mrow[64];
  __shared__ int s_tl;
  const int bid = blockIdx.x;
  const int tid = threadIdx.x;
  const int gtid = bid*NTH + tid;
  const int gstep = gridDim.x*NTH;
  const int nwarp = gridDim.x*(NTH/32);
  const int wid = bid*(NTH/32) + (tid>>5);
  const int lane = tid & 31;
  const float TINYF = 1.17549435e-38f;
  const float UNIADD = (float)(0.01/32.0);

#define POP(pid) ({ if (tid==0) s_tl = (int)atomicAdd(&g_ctr[pid], 1u); \
                    __syncthreads(); int _v = s_tl; _v; })

  for (int i = gtid; i < 6*T; i += gstep) g_ctr[i] = 0u;
  for (int i = gtid; i < B*D; i += gstep) g_deter[i] = 0.0f;
  for (int i = gtid; i < B*INX; i += gstep) {
    int b = i/INX, j = i - b*INX;
    g_xin[i] = (j < SC) ? 0.0f : actions[((size_t)b*T)*A_ + (j-SC)];
  }
  gridbar();

  for (int t = 0; t < T; t++) {
    // P1: h = (masked deter)@W_blk [128 tiles, IN=2048] ; x = silu(W_in@xin) [96, IN=1056]
    for (;;) {
      int tl = POP(t*6+0); if (tl >= 224) break;
      if (tl < 128)
        gemm_tile<0,1>(g_deter, D, W_blk, b_blk, g_h, D, D,
                       (tl/32)<<6, (tl%32)<<6, 0, isf, t, As, Ws, mrow);
      else {
        int i = tl - 128;
        gemm_tile<1,0>(g_xin, INX, W_in, b_in, g_x, X3H, INX,
                       (i/24)<<6, (i%24)<<6, 0, nullptr, 0, As, Ws, mrow);
      }
    }
    gridbar();
    // P2: gi = x@W_ih [384, IN=1536 heavy first] ; gh = blockdiag h@W_hh [384, IN=256]
    for (;;) {
      int tl = POP(t*6+1); if (tl >= 768) break;
      if (tl < 384)
        gemm_tile<0,0>(g_x, X3H, W_ih, b_ih, g_gi, NG, X3H,
                       (tl/96)<<6, (tl%96)<<6, 0, nullptr, 0, As, Ws, mrow);
      else {
        int i = tl - 384;
        int n0 = (i%96)<<6;
        gemm_tile<0,0>(g_h, D, W_hh, b_hh, g_gh, NG, BS,
                       (i/96)<<6, n0, (n0/G3)*BS, nullptr, 0, As, Ws, mrow);
      }
    }
    gridbar();
    // P3: GRU combine -> deter/out_deter/dein ; embed -> dein
    for (int i = gtid; i < B*D; i += gstep) {
      int b = i>>11, d = i & (D-1), k = d>>8, g = d & (BS-1);
      size_t base = (size_t)b*NG + k*G3 + g;
      float ir=g_gi[base], iz=g_gi[base+BS], inn=g_gi[base+2*BS];
      float hr=g_gh[base], hz=g_gh[base+BS], hnn=g_gh[base+2*BS];
      float r = 1.0f/(1.0f+expf(-(ir+hr)));
      float z = 1.0f/(1.0f+expf(-(iz+hz)));
      float n = tanhf(inn + r*hnn);
      float dv = (1.0f - z)*n + z*g_h[i];
      g_deter[i] = dv;
      g_dein[(size_t)b*DE_IN + d] = dv;
      out_deter[((size_t)b*T+t)*D + d] = dv;
    }
    for (int i = gtid; i < B*E; i += gstep) {
      int b = i>>10, j = i & (E-1);
      g_dein[(size_t)b*DE_IN + D + j] = embed[((size_t)b*T+t)*E + j];
    }
    gridbar();
    // P4: de = dein@W_proj [128 tiles, IN=3072]
    for (;;) {
      int tl = POP(t*6+2); if (tl >= 128) break;
      gemm_tile<0,0>(g_dein, DE_IN, W_proj, b_proj, g_de, D, DE_IN,
                     (tl/32)<<6, (tl%32)<<6, 0, nullptr, 0, As, Ws, mrow);
    }
    gridbar();
    // P5: h1c = silu([deter;de]@W1)  M=512 [64 tiles, IN=2048]
    for (;;) {
      int tl = POP(t*6+3); if (tl >= 64) break;
      int m0 = (tl/8)<<6, n0 = (tl%8)<<6;
      const float* Ap = (m0 < 256) ? g_deter : (g_de - (size_t)256*D);
      gemm_tile<1,0>(Ap, D, W1, b1, g_h1c, H, D, m0, n0, 0, nullptr, 0, As, Ws, mrow);
    }
    gridbar();
    // P6: h2c = silu(h1c@W2)  M=512 [64 tiles, IN=512]
    for (;;) {
      int tl = POP(t*6+4); if (tl >= 64) break;
      gemm_tile<1,0>(g_h1c, H, W2, b2, g_h2c, H, H,
                     (tl/8)<<6, (tl%8)<<6, 0, nullptr, 0, As, Ws, mrow);
    }
    gridbar();
    // P7: logits = h2c@W3  M=512 [128 tiles, IN=512]; rows<256 -> prior, else post
    for (;;) {
      int tl = POP(t*6+5); if (tl >= 128) break;
      int m0 = (tl/16)<<6, n0 = (tl%16)<<6;
      float* Cp = (m0 < 256) ? (out_prior + (size_t)t*SC)
                             : (out_post + (size_t)t*SC - (size_t)256*T*SC);
      gemm_tile<0,0>(g_h2c, H, W3, b3, Cp, T*SC, H, m0, n0, 0, nullptr, 0, As, Ws, mrow);
    }
    gridbar();
    // P8: sample -> out_stoch + next xin ; copy next actions
    {
      uint32_t k0, k1;
      threefry(0u, 42u, 0u, (uint32_t)t, k0, k1);   // fold_in(key(42), t)
      for (int gw = wid; gw < 128*32; gw += nwarp) {
        int b0 = gw >> 5, s = gw & 31;
        uint32_t nA = (uint32_t)(b0*SC + s*C + lane);
        uint32_t a0,a1,c0,c1;
        threefry(k0,k1,0u,nA,a0,a1);
        threefry(k0,k1,0u,nA + (uint32_t)(128*SC),c0,c1);
        uint32_t bitsH[2] = { a0^a1, c0^c1 };
#pragma unroll
        for (int half = 0; half < 2; half++) {
          int b = b0 + half*128;
          float lg = out_post[((size_t)b*T+t)*SC + s*C + lane];
          float m = lg;
          for (int o = 16; o; o >>= 1) m = fmaxf(m, __shfl_xor_sync(~0u, m, o));
          float e = expf(lg - m), sum = e;
          for (int o = 16; o; o >>= 1) sum += __shfl_xor_sync(~0u, sum, o);
          float p = 0.99f*(e/sum) + UNIADD;
          float uf = __uint_as_float((bitsH[half]>>9) | 0x3f800000u) - 1.0f;
          uf = fmaxf(uf + TINYF, TINYF);
          float val = -logf(-logf(uf)) + logf(p);
          float bv = val; int bidx = lane;
          for (int o = 16; o; o >>= 1) {
            float ov = __shfl_xor_sync(~0u, bv, o);
            int   oi = __shfl_xor_sync(~0u, bidx, o);
            if (ov > bv || (ov == bv && oi < bidx)) { bv = ov; bidx = oi; }
          }
          float oneh = (lane == bidx) ? 1.0f : 0.0f;
          out_stoch[((size_t)b*T+t)*SC + s*C + lane] = oneh;
          if (t + 1 < T)
            g_xin[(size_t)b*INX + s*C + lane] = isf[(size_t)b*T + t + 1] ? 0.0f : oneh;
        }
      }
      if (t + 1 < T)
        for (int i = gtid; i < B*A_; i += gstep) {
          int b = i>>5, a = i & 31;
          g_xin[(size_t)b*INX + SC + a] = actions[((size_t)b*T + t + 1)*A_ + a];
        }
    }
    gridbar();
  }
#undef POP
}

extern "C" void kernel_launch(void* const* d_in, const int* in_sizes, int n_in,
                              void* d_out, int out_size) {
  const float* embed  =(const float*)d_in[0];
  const float* actions=(const float*)d_in[1];
  const int*   isf    =(const int*)  d_in[2];
  const float* W_in =(const float*)d_in[5],  *b_in =(const float*)d_in[6];
  const float* W_blk=(const float*)d_in[7],  *b_blk=(const float*)d_in[8];
  const float* W_ih =(const float*)d_in[9],  *b_ih =(const float*)d_in[10];
  const float* W_hh =(const float*)d_in[11], *b_hh =(const float*)d_in[12];
  const float* W1   =(const float*)d_in[13], *b1   =(const float*)d_in[14];
  const float* W2   =(const float*)d_in[15], *b2   =(const float*)d_in[16];
  const float* W3   =(const float*)d_in[17], *b3   =(const float*)d_in[18];
  const float* W_proj=(const float*)d_in[19],*b_proj=(const float*)d_in[20];

  float* out = (float*)d_out;
  float* out_deter = out;                          // [B,T,D]
  float* out_stoch = out + (size_t)B*T*D;          // [B,T,S,C]
  float* out_prior = out_stoch + (size_t)B*T*SC;   // [B,T,S,C]
  float* out_post  = out_prior + (size_t)B*T*SC;   // [B,T,S,C]

  k_rssm<<<NBLK, NTH>>>(embed, actions, isf,
                        W_in, b_in, W_blk, b_blk, W_ih, b_ih, W_hh, b_hh,
                        W1, b1, W2, b2, W3, b3, W_proj, b_proj,
                        out_deter, out_stoch, out_prior, out_post);
}

// round 7
// speedup vs baseline: 1.4161x; 1.4161x over previous
#include <cuda_runtime.h>
#include <cstdint>
#include <cstddef>

constexpr int B=256, T=64, H=512, D=2048, S=32, C=32, A_=32, E=1024, BS=256;
constexpr int X3H=1536, INX=1056, G3=768, NG=6144, DE_IN=3072, SC=1024;
constexpr int NBLK=296, NTH=256;

__device__ __align__(16) float g_deter[B*D];
__device__ __align__(16) float g_xin [B*INX];
__device__ __align__(16) float g_xp0 [B*X3H];
__device__ __align__(16) float g_xp1 [B*X3H];
__device__ __align__(16) float g_hp0 [B*D];
__device__ __align__(16) float g_hp1 [B*D];
__device__ __align__(16) float g_gi  [B*NG];
__device__ __align__(16) float g_gh  [B*NG];
__device__ __align__(16) float g_dein[B*DE_IN];
__device__ __align__(16) float g_dp0 [B*D];
__device__ __align__(16) float g_dp1 [B*D];
__device__ __align__(16) float g_h1a [2*B*H];  // rows 0..255 prior, 256..511 post
__device__ __align__(16) float g_h1b [2*B*H];
__device__ __align__(16) float g_h2a [2*B*H];
__device__ __align__(16) float g_h2b [2*B*H];
__device__ __align__(16) float g_lpa [2*B*SC];
__device__ __align__(16) float g_lpb [2*B*SC];
__device__ unsigned g_cnt;
__device__ unsigned g_gen;
__device__ unsigned g_ctr[6*T];

// ----------------------------- grid barrier --------------------------------
__device__ __forceinline__ void gridbar() {
  __syncthreads();
  if (threadIdx.x == 0) {
    unsigned gen = *(volatile unsigned*)&g_gen;
    __threadfence();
    if (atomicAdd(&g_cnt, 1u) == gridDim.x - 1u) {
      g_cnt = 0u;
      __threadfence();
      atomicExch(&g_gen, gen + 1u);
    } else {
      while (*(volatile unsigned*)&g_gen == gen) {}
    }
    __threadfence();
  }
  __syncthreads();
}

// ------------------------------ threefry2x32 -------------------------------
__device__ __forceinline__ void threefry(uint32_t k0, uint32_t k1, uint32_t x0,
                                         uint32_t x1, uint32_t& o0, uint32_t& o1) {
  uint32_t ks2 = 0x1BD11BDAu ^ k0 ^ k1;
#define TFR(x,r) x = (x<<r)|(x>>(32-r))
#define TF4(a,b,c,d) x0+=x1;TFR(x1,a);x1^=x0; x0+=x1;TFR(x1,b);x1^=x0; x0+=x1;TFR(x1,c);x1^=x0; x0+=x1;TFR(x1,d);x1^=x0;
  x0 += k0; x1 += k1;
  TF4(13,15,26,6);  x0 += k1;  x1 += ks2 + 1u;
  TF4(17,29,16,24); x0 += ks2; x1 += k0 + 2u;
  TF4(13,15,26,6);  x0 += k0;  x1 += k1 + 3u;
  TF4(17,29,16,24); x0 += k1;  x1 += ks2 + 4u;
  TF4(13,15,26,6);  x0 += ks2; x1 += k0 + 5u;
  o0 = x0; o1 = x1;
#undef TF4
#undef TFR
}

__device__ __forceinline__ float silu1(float v) { return v/(1.0f+expf(-v)); }

// ------------------------------ GEMM tile ----------------------------------
// C[m,n] = sum_{k in [kbase,kbase+IN2)} Aeff[m,k]*W[n,k] (+ bias if WMODE==0)
// AMODE: 0 = A0 plain ; 1 = (A0+A1)+Abias ; 2 = silu((A0+A1)+Abias)
// 64x64 tile, BK=16, 256 threads, 4x4 register tile.
template <int AMODE, int WMODE, int MASKED>
__device__ __forceinline__ void gemm_tile(
    const float* __restrict__ A0, const float* __restrict__ A1,
    const float* __restrict__ Abias, int lda,
    const float* __restrict__ W, const float* __restrict__ bias,
    float* __restrict__ Cb, int ldc,
    int IN2, int kbase, int m0, int n0, int aColBase,
    const int* __restrict__ isf, int t,
    float (*As)[68], float (*Ws)[68], float* mrow) {
  const int tid = threadIdx.x;
  if (MASKED) { if (tid < 64) mrow[tid] = isf[(size_t)(m0+tid)*T + t] ? 0.0f : 1.0f; }
  __syncthreads();
  const int aoff = aColBase + kbase;
  const float* Ab0 = A0 + (size_t)m0*lda + aoff;
  const float* Ab1 = (AMODE>=1) ? (A1 + (size_t)m0*lda + aoff) : nullptr;
  const float* Wb  = W + (size_t)n0*(/*full IN of W rows*/0) ;  // unused; W addressed below
  const int lr = tid>>2, lq = (tid&3)<<2, ty = tid>>4, tx = tid&15;
  float acc[4][4] = {};
  for (int k0 = 0; k0 < IN2; k0 += 16) {
    float4 av;
    if (AMODE == 0) {
      av = *(const float4*)(Ab0 + (size_t)lr*lda + k0 + lq);
    } else {
      float4 a0 = *(const float4*)(Ab0 + (size_t)lr*lda + k0 + lq);
      float4 a1 = *(const float4*)(Ab1 + (size_t)lr*lda + k0 + lq);
      float4 ab = *(const float4*)(Abias + aoff + k0 + lq);
      av.x = (a0.x + a1.x) + ab.x; av.y = (a0.y + a1.y) + ab.y;
      av.z = (a0.z + a1.z) + ab.z; av.w = (a0.w + a1.w) + ab.w;
      if (AMODE == 2) { av.x=silu1(av.x); av.y=silu1(av.y); av.z=silu1(av.z); av.w=silu1(av.w); }
    }
    float4 wv = *(const float4*)(W + (size_t)(n0+lr)*/*INfull*/(lda==0?0:0) + 0); // placeholder
    (void)wv; (void)Wb;
    // NOTE: real W load below
    float mm = MASKED ? mrow[lr] : 1.0f;
    As[lq+0][lr]=av.x*mm; As[lq+1][lr]=av.y*mm;
    As[lq+2][lr]=av.z*mm; As[lq+3][lr]=av.w*mm;
    __syncthreads();  // placeholder; replaced by unified path
    __syncthreads();
  }
  (void)acc; (void)ty; (void)tx; (void)Cb; (void)ldc; (void)bias;
}

// The placeholder above is unused; the real implementation takes the W row
// stride explicitly.  (kept minimal to avoid template bloat)
template <int AMODE, int WMODE, int MASKED>
__device__ __forceinline__ void gemm64(
    const float* __restrict__ A0, const float* __restrict__ A1,
    const float* __restrict__ Abias, int lda,
    const float* __restrict__ W, int ldw, const float* __restrict__ bias,
    float* __restrict__ Cb, int ldc,
    int IN2, int kbase, int m0, int n0, int aColBase,
    const int* __restrict__ isf, int t,
    float (*As)[68], float (*Ws)[68], float* mrow) {
  const int tid = threadIdx.x;
  if (MASKED) { if (tid < 64) mrow[tid] = isf[(size_t)(m0+tid)*T + t] ? 0.0f : 1.0f; }
  __syncthreads();
  const int aoff = aColBase + kbase;
  const float* Ab0 = A0 + (size_t)m0*lda + aoff;
  const float* Ab1 = (AMODE>=1) ? (A1 + (size_t)m0*lda + aoff) : nullptr;
  const float* Wb  = W + (size_t)n0*ldw + kbase;
  const int lr = tid>>2, lq = (tid&3)<<2, ty = tid>>4, tx = tid&15;
  float acc[4][4] = {};
  for (int k0 = 0; k0 < IN2; k0 += 16) {
    float4 av;
    if (AMODE == 0) {
      av = *(const float4*)(Ab0 + (size_t)lr*lda + k0 + lq);
    } else {
      float4 a0 = *(const float4*)(Ab0 + (size_t)lr*lda + k0 + lq);
      float4 a1 = *(const float4*)(Ab1 + (size_t)lr*lda + k0 + lq);
      float4 ab = *(const float4*)(Abias + aoff + k0 + lq);
      av.x = (a0.x + a1.x) + ab.x; av.y = (a0.y + a1.y) + ab.y;
      av.z = (a0.z + a1.z) + ab.z; av.w = (a0.w + a1.w) + ab.w;
      if (AMODE == 2) { av.x=silu1(av.x); av.y=silu1(av.y); av.z=silu1(av.z); av.w=silu1(av.w); }
    }
    float4 wv = *(const float4*)(Wb + (size_t)lr*ldw + k0 + lq);
    float mm = MASKED ? mrow[lr] : 1.0f;
    As[lq+0][lr]=av.x*mm; As[lq+1][lr]=av.y*mm;
    As[lq+2][lr]=av.z*mm; As[lq+3][lr]=av.w*mm;
    Ws[lq+0][lr]=wv.x; Ws[lq+1][lr]=wv.y; Ws[lq+2][lr]=wv.z; Ws[lq+3][lr]=wv.w;
    __syncthreads();
#pragma unroll
    for (int kk = 0; kk < 16; kk++) {
      float4 a = *(const float4*)&As[kk][ty<<2];
      float4 w = *(const float4*)&Ws[kk][tx<<2];
      acc[0][0]+=a.x*w.x; acc[0][1]+=a.x*w.y; acc[0][2]+=a.x*w.z; acc[0][3]+=a.x*w.w;
      acc[1][0]+=a.y*w.x; acc[1][1]+=a.y*w.y; acc[1][2]+=a.y*w.z; acc[1][3]+=a.y*w.w;
      acc[2][0]+=a.z*w.x; acc[2][1]+=a.z*w.y; acc[2][2]+=a.z*w.z; acc[2][3]+=a.z*w.w;
      acc[3][0]+=a.w*w.x; acc[3][1]+=a.w*w.y; acc[3][2]+=a.w*w.z; acc[3][3]+=a.w*w.w;
    }
    __syncthreads();
  }
#pragma unroll
  for (int r = 0; r < 4; r++) {
    int mi = m0 + (ty<<2) + r;
    int nb = n0 + (tx<<2);
    float4 v;
    if (WMODE == 0) {
      float4 bv = *(const float4*)(bias + nb);
      v.x = acc[r][0] + bv.x; v.y = acc[r][1] + bv.y;
      v.z = acc[r][2] + bv.z; v.w = acc[r][3] + bv.w;
    } else {
      v.x = acc[r][0]; v.y = acc[r][1]; v.z = acc[r][2]; v.w = acc[r][3];
    }
    *(float4*)(Cb + (size_t)mi*ldc + nb) = v;
  }
}

// ------------------------------ megakernel ---------------------------------
__global__ void __launch_bounds__(NTH, 2) k_rssm(
    const float* __restrict__ embed, const float* __restrict__ actions,
    const int* __restrict__ isf,
    const float* __restrict__ W_in,  const float* __restrict__ b_in,
    const float* __restrict__ W_blk, const float* __restrict__ b_blk,
    const float* __restrict__ W_ih,  const float* __restrict__ b_ih,
    const float* __restrict__ W_hh,  const float* __restrict__ b_hh,
    const float* __restrict__ W1,    const float* __restrict__ b1,
    const float* __restrict__ W2,    const float* __restrict__ b2,
    const float* __restrict__ W3,    const float* __restrict__ b3,
    const float* __restrict__ W_proj,const float* __restrict__ b_proj,
    float* __restrict__ out_deter, float* __restrict__ out_stoch,
    float* __restrict__ out_prior, float* __restrict__ out_post) {
  __shared__ __align__(16) float As[16][68];
  __shared__ __align__(16) float Ws[16][68];
  __shared__ float mrow[64];
  __shared__ int s_tl;
  const int bid = blockIdx.x;
  const int tid = threadIdx.x;
  const int gtid = bid*NTH + tid;
  const int gstep = gridDim.x*NTH;
  const int nwarp = gridDim.x*(NTH/32);
  const int wid = bid*(NTH/32) + (tid>>5);
  const int lane = tid & 31;
  const float TINYF = 1.17549435e-38f;
  const float UNIADD = (float)(0.01/32.0);

#define POP(pid) ({ if (tid==0) s_tl = (int)atomicAdd(&g_ctr[pid], 1u); \
                    __syncthreads(); int _v = s_tl; _v; })

  for (int i = gtid; i < 6*T; i += gstep) g_ctr[i] = 0u;
  for (int i = gtid; i < B*D; i += gstep) g_deter[i] = 0.0f;
  for (int i = gtid; i < B*INX; i += gstep) {
    int b = i/INX, j = i - b*INX;
    g_xin[i] = (j < SC) ? 0.0f : actions[((size_t)b*T)*A_ + (j-SC)];
  }
  gridbar();

  for (int t = 0; t < T; t++) {
    // P1: h partials (deter@W_blk, split-K 2, 256 tiles x 64ch)
    //     x partials (xin@W_in, split-K 2, 192 tiles x 33ch)
    for (;;) {
      int tl = POP(t*6+0); if (tl >= 448) break;
      if (tl < 256) {
        int p = tl>>7, i = tl&127;
        gemm64<0,1,1>(g_deter,nullptr,nullptr,D, W_blk,D,nullptr,
                      p? g_hp1:g_hp0, D, D/2, p*(D/2),
                      (i/32)<<6,(i%32)<<6, 0, isf, t, As, Ws, mrow);
      } else {
        int j = tl-256, p = j/96, i = j%96;
        gemm64<0,1,0>(g_xin,nullptr,nullptr,INX, W_in,INX,nullptr,
                      p? g_xp1:g_xp0, X3H, INX/2, p*(INX/2),
                      (i/24)<<6,(i%24)<<6, 0, nullptr,0, As, Ws, mrow);
      }
    }
    gridbar();
    // P2: gi = silu(x)@W_ih [384 tiles x 96ch]; gh = blockdiag h@W_hh [384 x 16ch]
    for (;;) {
      int tl = POP(t*6+1); if (tl >= 768) break;
      if (tl < 384)
        gemm64<2,0,0>(g_xp0,g_xp1,b_in,X3H, W_ih,X3H,b_ih, g_gi,NG, X3H,0,
                      (tl/96)<<6,(tl%96)<<6, 0, nullptr,0, As, Ws, mrow);
      else {
        int i = tl-384, n0 = (i%96)<<6;
        gemm64<1,0,0>(g_hp0,g_hp1,b_blk,D, W_hh,BS,b_hh, g_gh,NG, BS,0,
                      (i/96)<<6,n0, (n0/G3)*BS, nullptr,0, As, Ws, mrow);
      }
    }
    gridbar();
    // P3: GRU combine -> deter/out_deter/dein ; embed -> dein
    for (int i = gtid; i < B*D; i += gstep) {
      int b = i>>11, d = i & (D-1), k = d>>8, g = d & (BS-1);
      size_t base = (size_t)b*NG + k*G3 + g;
      float ir=g_gi[base], iz=g_gi[base+BS], inn=g_gi[base+2*BS];
      float hr=g_gh[base], hz=g_gh[base+BS], hnn=g_gh[base+2*BS];
      float hv = (g_hp0[i] + g_hp1[i]) + b_blk[d];
      float r = 1.0f/(1.0f+expf(-(ir+hr)));
      float z = 1.0f/(1.0f+expf(-(iz+hz)));
      float n = tanhf(inn + r*hnn);
      float dv = (1.0f - z)*n + z*hv;
      g_deter[i] = dv;
      g_dein[(size_t)b*DE_IN + d] = dv;
      out_deter[((size_t)b*T+t)*D + d] = dv;
    }
    for (int i = gtid; i < B*E; i += gstep) {
      int b = i>>10, j = i & (E-1);
      g_dein[(size_t)b*DE_IN + D + j] = embed[((size_t)b*T+t)*E + j];
    }
    gridbar();
    // P4: de partials (dein@W_proj, split-K 2, 256 tiles x 96ch)
    for (;;) {
      int tl = POP(t*6+2); if (tl >= 256) break;
      int p = tl>>7, i = tl&127;
      gemm64<0,1,0>(g_dein,nullptr,nullptr,DE_IN, W_proj,DE_IN,nullptr,
                    p? g_dp1:g_dp0, D, DE_IN/2, p*(DE_IN/2),
                    (i/32)<<6,(i%32)<<6, 0, nullptr,0, As, Ws, mrow);
    }
    gridbar();
    // P5: h1 partials, M=512 ([deter ; de+bias]) @ W1, split-K 2 [128 x 64ch]
    for (;;) {
      int tl = POP(t*6+3); if (tl >= 128) break;
      int p = tl>>6, i = tl&63;
      int m0 = (i/8)<<6, n0 = (i%8)<<6;
      float* Cp = p? g_h1b : g_h1a;
      if (m0 < 256)
        gemm64<0,1,0>(g_deter,nullptr,nullptr,D, W1,D,nullptr, Cp,H,
                      D/2, p*(D/2), m0,n0, 0, nullptr,0, As, Ws, mrow);
      else
        gemm64<1,1,0>(g_dp0-(size_t)256*D, g_dp1-(size_t)256*D, b_proj, D,
                      W1,D,nullptr, Cp,H, D/2, p*(D/2), m0,n0, 0, nullptr,0, As, Ws, mrow);
    }
    gridbar();
    // P6: h2 partials = silu(h1)@W2, M=512, split-K 2 [128 x 16ch]
    for (;;) {
      int tl = POP(t*6+4); if (tl >= 128) break;
      int p = tl>>6, i = tl&63;
      gemm64<2,1,0>(g_h1a,g_h1b,b1,H, W2,H,nullptr, p? g_h2b:g_h2a, H,
                    H/2, p*(H/2), (i/8)<<6,(i%8)<<6, 0, nullptr,0, As, Ws, mrow);
    }
    gridbar();
    // P7: logit partials = silu(h2)@W3, M=512, split-K 2 [256 x 16ch]
    for (;;) {
      int tl = POP(t*6+5); if (tl >= 256) break;
      int p = tl>>7, i = tl&127;
      gemm64<2,1,0>(g_h2a,g_h2b,b2,H, W3,H,nullptr, p? g_lpb:g_lpa, SC,
                    H/2, p*(H/2), (i/16)<<6,(i%16)<<6, 0, nullptr,0, As, Ws, mrow);
    }
    gridbar();
    // P8: prior combine -> out_prior ; sample(post combine) -> out_post/out_stoch/xin
    for (int i = gtid; i < B*SC; i += gstep) {
      int b = i>>10, j = i & (SC-1);
      out_prior[((size_t)b*T+t)*SC + j] = (g_lpa[i] + g_lpb[i]) + b3[j];
    }
    {
      uint32_t k0, k1;
      threefry(0u, 42u, 0u, (uint32_t)t, k0, k1);   // fold_in(key(42), t)
      for (int gw = wid; gw < 128*32; gw += nwarp) {
        int b0 = gw >> 5, s = gw & 31;
        uint32_t nA = (uint32_t)(b0*SC + s*C + lane);
        uint32_t a0,a1,c0,c1;
        threefry(k0,k1,0u,nA,a0,a1);
        threefry(k0,k1,0u,nA + (uint32_t)(128*SC),c0,c1);
        uint32_t bitsH[2] = { a0^a1, c0^c1 };
#pragma unroll
        for (int half = 0; half < 2; half++) {
          int b = b0 + half*128;
          size_t li = (size_t)(256+b)*SC + s*C + lane;
          float lg = (g_lpa[li] + g_lpb[li]) + b3[s*C + lane];
          out_post[((size_t)b*T+t)*SC + s*C + lane] = lg;
          float m = lg;
          for (int o = 16; o; o >>= 1) m = fmaxf(m, __shfl_xor_sync(~0u, m, o));
          float e = expf(lg - m), sum = e;
          for (int o = 16; o; o >>= 1) sum += __shfl_xor_sync(~0u, sum, o);
          float p = 0.99f*(e/sum) + UNIADD;
          float uf = __uint_as_float((bitsH[half]>>9) | 0x3f800000u) - 1.0f;
          uf = fmaxf(uf + TINYF, TINYF);
          float val = -logf(-logf(uf)) + logf(p);
          float bv = val; int bidx = lane;
          for (int o = 16; o; o >>= 1) {
            float ov = __shfl_xor_sync(~0u, bv, o);
            int   oi = __shfl_xor_sync(~0u, bidx, o);
            if (ov > bv || (ov == bv && oi < bidx)) { bv = ov; bidx = oi; }
          }
          float oneh = (lane == bidx) ? 1.0f : 0.0f;
          out_stoch[((size_t)b*T+t)*SC + s*C + lane] = oneh;
          if (t + 1 < T)
            g_xin[(size_t)b*INX + s*C + lane] = isf[(size_t)b*T + t + 1] ? 0.0f : oneh;
        }
      }
      if (t + 1 < T)
        for (int i = gtid; i < B*A_; i += gstep) {
          int b = i>>5, a = i & 31;
          g_xin[(size_t)b*INX + SC + a] = actions[((size_t)b*T + t + 1)*A_ + a];
        }
    }
    gridbar();
  }
#undef POP
}

extern "C" void kernel_launch(void* const* d_in, const int* in_sizes, int n_in,
                              void* d_out, int out_size) {
  const float* embed  =(const float*)d_in[0];
  const float* actions=(const float*)d_in[1];
  const int*   isf    =(const int*)  d_in[2];
  const float* W_in =(const float*)d_in[5],  *b_in =(const float*)d_in[6];
  const float* W_blk=(const float*)d_in[7],  *b_blk=(const float*)d_in[8];
  const float* W_ih =(const float*)d_in[9],  *b_ih =(const float*)d_in[10];
  const float* W_hh =(const float*)d_in[11], *b_hh =(const float*)d_in[12];
  const float* W1   =(const float*)d_in[13], *b1   =(const float*)d_in[14];
  const float* W2   =(const float*)d_in[15], *b2   =(const float*)d_in[16];
  const float* W3   =(const float*)d_in[17], *b3   =(const float*)d_in[18];
  const float* W_proj=(const float*)d_in[19],*b_proj=(const float*)d_in[20];

  float* out = (float*)d_out;
  float* out_deter = out;                          // [B,T,D]
  float* out_stoch = out + (size_t)B*T*D;          // [B,T,S,C]
  float* out_prior = out_stoch + (size_t)B*T*SC;   // [B,T,S,C]
  float* out_post  = out_prior + (size_t)B*T*SC;   // [B,T,S,C]

  k_rssm<<<NBLK, NTH>>>(embed, actions, isf,
                        W_in, b_in, W_blk, b_blk, W_ih, b_ih, W_hh, b_hh,
                        W1, b1, W2, b2, W3, b3, W_proj, b_proj,
                        out_deter, out_stoch, out_prior, out_post);
}